// round 1
// baseline (speedup 1.0000x reference)
#include <cuda_runtime.h>
#include <math.h>

#define BATCH 4
#define SEQ   4096
#define DIN   1024
#define DH    128

// Scratch for projected q, k, v  (each [BATCH*SEQ, DH] fp32 = 8 MB)
__device__ float g_q[BATCH * SEQ * DH];
__device__ float g_k[BATCH * SEQ * DH];
__device__ float g_v[BATCH * SEQ * DH];

// ---------------------------------------------------------------------------
// Projection: C[M,128] = A[M,1024] @ W[1024,128] + bias, M = 16384
// Classic register-tiled SGEMM: BM=128, BN=128(full), BK=16, 256 threads,
// each thread 8x8 accumulators. blockIdx.y selects {q,k,v}.
// ---------------------------------------------------------------------------
#define PBM 128
#define PBK 16

__global__ __launch_bounds__(256)
void proj_kernel(const float* __restrict__ in_q, const float* __restrict__ in_k,
                 const float* __restrict__ in_v,
                 const float* __restrict__ Wq, const float* __restrict__ bq,
                 const float* __restrict__ Wk, const float* __restrict__ bk,
                 const float* __restrict__ Wv, const float* __restrict__ bv)
{
    __shared__ float As[PBK][PBM];   // A tile, k-major (transposed on store)
    __shared__ float Bs[PBK][DH];    // W tile

    const float* A; const float* W; const float* bias; float* C;
    int which = blockIdx.y;
    if (which == 0)      { A = in_q; W = Wq; bias = bq; C = g_q; }
    else if (which == 1) { A = in_k; W = Wk; bias = bk; C = g_k; }
    else                 { A = in_v; W = Wv; bias = bv; C = g_v; }

    const int row0 = blockIdx.x * PBM;
    const int tid  = threadIdx.x;
    const int tx   = tid & 15;
    const int ty   = tid >> 4;

    float acc[8][8];
    #pragma unroll
    for (int i = 0; i < 8; i++)
        #pragma unroll
        for (int j = 0; j < 8; j++) acc[i][j] = 0.0f;

    for (int k0 = 0; k0 < DIN; k0 += PBK) {
        // A tile: 128 rows x 16 cols (2048 floats / 256 thr = 2 float4 each)
        #pragma unroll
        for (int t = 0; t < 2; t++) {
            int e = (tid + t * 256) * 4;   // 0..2044
            int r = e >> 4;                // 0..127
            int c = e & 15;                // 0,4,8,12
            float4 v = *(const float4*)(A + (size_t)(row0 + r) * DIN + k0 + c);
            As[c + 0][r] = v.x; As[c + 1][r] = v.y;
            As[c + 2][r] = v.z; As[c + 3][r] = v.w;
        }
        // W tile: 16 rows x 128 cols
        #pragma unroll
        for (int t = 0; t < 2; t++) {
            int e = (tid + t * 256) * 4;   // 0..2044
            int r = e >> 7;                // 0..15
            int c = e & 127;
            *(float4*)&Bs[r][c] = *(const float4*)(W + (size_t)(k0 + r) * DH + c);
        }
        __syncthreads();

        #pragma unroll
        for (int kk = 0; kk < PBK; kk++) {
            float a[8], b[8];
            #pragma unroll
            for (int i = 0; i < 8; i++) a[i] = As[kk][ty * 8 + i];
            #pragma unroll
            for (int j = 0; j < 8; j++) b[j] = Bs[kk][tx + 16 * j];  // conflict-free
            #pragma unroll
            for (int i = 0; i < 8; i++)
                #pragma unroll
                for (int j = 0; j < 8; j++)
                    acc[i][j] += a[i] * b[j];
        }
        __syncthreads();
    }

    #pragma unroll
    for (int j = 0; j < 8; j++) {
        int c = tx + 16 * j;
        float bb = bias[c];
        #pragma unroll
        for (int i = 0; i < 8; i++) {
            int r = row0 + ty * 8 + i;
            C[(size_t)r * DH + c] = acc[i][j] + bb;   // coalesced over tx
        }
    }
}

// ---------------------------------------------------------------------------
// Flash attention: per block 64 queries, loop 64-key tiles, online softmax.
// 256 threads as 16x16: thread owns S rows ty*4+i, S cols tx+16*j,
// O cols tx+16*c. All smem reads conflict-free scalar LDS.
// ---------------------------------------------------------------------------
#define AQ 64
#define AK 64
#define QS_STRIDE 129
#define KV_STRIDE 129
#define PS_STRIDE 65

__global__ __launch_bounds__(256)
void attn_kernel(float* __restrict__ out)
{
    extern __shared__ float smem[];
    float* Qs  = smem;                         // AQ * QS_STRIDE
    float* KVs = Qs + AQ * QS_STRIDE;          // AK * KV_STRIDE (K then V, reused)
    float* Ps  = KVs + AK * KV_STRIDE;         // AQ * PS_STRIDE

    const int tid = threadIdx.x;
    const int tx  = tid & 15;
    const int ty  = tid >> 4;
    const int batch = blockIdx.y;
    const int q0    = blockIdx.x * AQ;

    const float* qb = g_q + (size_t)batch * SEQ * DH;
    const float* kb = g_k + (size_t)batch * SEQ * DH;
    const float* vb = g_v + (size_t)batch * SEQ * DH;

    const float scale = 0.08838834764831845f;  // 1/sqrt(128), folded into Q

    // Load Q tile (pre-scaled)
    #pragma unroll
    for (int t = 0; t < 8; t++) {
        int e = (tid + t * 256) * 4;   // 0..8188
        int r = e >> 7;
        int c = e & 127;
        float4 v = *(const float4*)(qb + (size_t)(q0 + r) * DH + c);
        Qs[r * QS_STRIDE + c + 0] = v.x * scale;
        Qs[r * QS_STRIDE + c + 1] = v.y * scale;
        Qs[r * QS_STRIDE + c + 2] = v.z * scale;
        Qs[r * QS_STRIDE + c + 3] = v.w * scale;
    }

    float m[4], l[4], o[4][8];
    #pragma unroll
    for (int i = 0; i < 4; i++) {
        m[i] = -1e30f; l[i] = 0.0f;
        #pragma unroll
        for (int c = 0; c < 8; c++) o[i][c] = 0.0f;
    }

    for (int kv0 = 0; kv0 < SEQ; kv0 += AK) {
        // ---- load K tile ----
        #pragma unroll
        for (int t = 0; t < 8; t++) {
            int e = (tid + t * 256) * 4;
            int r = e >> 7;
            int c = e & 127;
            float4 v = *(const float4*)(kb + (size_t)(kv0 + r) * DH + c);
            KVs[r * KV_STRIDE + c + 0] = v.x;
            KVs[r * KV_STRIDE + c + 1] = v.y;
            KVs[r * KV_STRIDE + c + 2] = v.z;
            KVs[r * KV_STRIDE + c + 3] = v.w;
        }
        __syncthreads();

        // ---- S = Qs @ K^T  (thread: 4 rows x 4 strided cols) ----
        float s[4][4];
        #pragma unroll
        for (int i = 0; i < 4; i++)
            #pragma unroll
            for (int j = 0; j < 4; j++) s[i][j] = 0.0f;

        #pragma unroll 4
        for (int d = 0; d < DH; d++) {
            float a[4], b[4];
            #pragma unroll
            for (int i = 0; i < 4; i++) a[i] = Qs[(ty * 4 + i) * QS_STRIDE + d];
            #pragma unroll
            for (int j = 0; j < 4; j++) b[j] = KVs[(tx + 16 * j) * KV_STRIDE + d];
            #pragma unroll
            for (int i = 0; i < 4; i++)
                #pragma unroll
                for (int j = 0; j < 4; j++)
                    s[i][j] += a[i] * b[j];
        }

        // ---- online softmax (row groups = 16 lanes sharing ty) ----
        #pragma unroll
        for (int i = 0; i < 4; i++) {
            float tm = s[i][0];
            #pragma unroll
            for (int j = 1; j < 4; j++) tm = fmaxf(tm, s[i][j]);
            #pragma unroll
            for (int off = 8; off > 0; off >>= 1)
                tm = fmaxf(tm, __shfl_xor_sync(0xffffffffu, tm, off));

            float mn = fmaxf(m[i], tm);
            float corr = __expf(m[i] - mn);
            m[i] = mn;
            l[i] *= corr;
            #pragma unroll
            for (int c = 0; c < 8; c++) o[i][c] *= corr;

            float rs = 0.0f;
            #pragma unroll
            for (int j = 0; j < 4; j++) {
                float p = __expf(s[i][j] - mn);
                s[i][j] = p;
                rs += p;
            }
            #pragma unroll
            for (int off = 8; off > 0; off >>= 1)
                rs += __shfl_xor_sync(0xffffffffu, rs, off);
            l[i] += rs;

            #pragma unroll
            for (int j = 0; j < 4; j++)
                Ps[(ty * 4 + i) * PS_STRIDE + tx + 16 * j] = s[i][j];
        }
        __syncthreads();   // Ps visible; everyone done reading K

        // ---- load V tile (overwrite KV buffer) ----
        #pragma unroll
        for (int t = 0; t < 8; t++) {
            int e = (tid + t * 256) * 4;
            int r = e >> 7;
            int c = e & 127;
            float4 v = *(const float4*)(vb + (size_t)(kv0 + r) * DH + c);
            KVs[r * KV_STRIDE + c + 0] = v.x;
            KVs[r * KV_STRIDE + c + 1] = v.y;
            KVs[r * KV_STRIDE + c + 2] = v.z;
            KVs[r * KV_STRIDE + c + 3] = v.w;
        }
        __syncthreads();

        // ---- O += P @ V ----
        #pragma unroll 4
        for (int k = 0; k < AK; k++) {
            float a[4], b[8];
            #pragma unroll
            for (int i = 0; i < 4; i++) a[i] = Ps[(ty * 4 + i) * PS_STRIDE + k];
            #pragma unroll
            for (int c = 0; c < 8; c++) b[c] = KVs[k * KV_STRIDE + tx + 16 * c];
            #pragma unroll
            for (int i = 0; i < 4; i++)
                #pragma unroll
                for (int c = 0; c < 8; c++)
                    o[i][c] += a[i] * b[c];
        }
        __syncthreads();   // done reading V before next K overwrite
    }

    // ---- epilogue: normalize and store (coalesced over tx) ----
    float* ob = out + (size_t)batch * SEQ * DH;
    #pragma unroll
    for (int i = 0; i < 4; i++) {
        float inv = 1.0f / l[i];
        int r = q0 + ty * 4 + i;
        #pragma unroll
        for (int c = 0; c < 8; c++)
            ob[(size_t)r * DH + tx + 16 * c] = o[i][c] * inv;
    }
}

// ---------------------------------------------------------------------------
extern "C" void kernel_launch(void* const* d_in, const int* in_sizes, int n_in,
                              void* d_out, int out_size)
{
    const float* query = (const float*)d_in[0];
    const float* key   = (const float*)d_in[1];
    const float* value = (const float*)d_in[2];
    const float* Wq    = (const float*)d_in[3];
    const float* bq    = (const float*)d_in[4];
    const float* Wk    = (const float*)d_in[5];
    const float* bk    = (const float*)d_in[6];
    const float* Wv    = (const float*)d_in[7];
    const float* bv    = (const float*)d_in[8];
    float* out = (float*)d_out;

    // Projections: 128 row-tiles x {q,k,v}
    dim3 pgrid((BATCH * SEQ) / PBM, 3);
    proj_kernel<<<pgrid, 256>>>(query, key, value, Wq, bq, Wk, bk, Wv, bv);

    // Flash attention
    size_t smem_bytes = (size_t)(AQ * QS_STRIDE + AK * KV_STRIDE + AQ * PS_STRIDE)
                        * sizeof(float);   // 82,688 B
    cudaFuncSetAttribute(attn_kernel,
                         cudaFuncAttributeMaxDynamicSharedMemorySize,
                         (int)smem_bytes);
    dim3 agrid(SEQ / AQ, BATCH);
    attn_kernel<<<agrid, 256, smem_bytes>>>(out);
}

// round 2
// speedup vs baseline: 2.9191x; 2.9191x over previous
#include <cuda_runtime.h>
#include <math.h>

#define BATCH 4
#define SEQ   4096
#define DIN   1024
#define DH    128

// Scratch for projected q, k, v  (each [BATCH*SEQ, DH] fp32 = 8 MB)
__device__ float g_q[BATCH * SEQ * DH];
__device__ float g_k[BATCH * SEQ * DH];
__device__ float g_v[BATCH * SEQ * DH];

// ---------------------------------------------------------------------------
// tf32 helpers
// ---------------------------------------------------------------------------
__device__ __forceinline__ unsigned f2tf(float x) {
    unsigned u;
    asm("cvt.rna.tf32.f32 %0, %1;" : "=r"(u) : "f"(x));
    return u;
}

__device__ __forceinline__ uint4 f2tf4(float4 v) {
    return make_uint4(f2tf(v.x), f2tf(v.y), f2tf(v.z), f2tf(v.w));
}

// D(m16n8) += A(m16k8, row) * B(k8n8, col);  A,B tf32; C,D fp32
__device__ __forceinline__ void mma8(float* c,
                                     unsigned a0, unsigned a1, unsigned a2, unsigned a3,
                                     unsigned b0, unsigned b1) {
    asm volatile(
        "mma.sync.aligned.m16n8k8.row.col.f32.tf32.tf32.f32 "
        "{%0,%1,%2,%3}, {%4,%5,%6,%7}, {%8,%9}, {%0,%1,%2,%3};\n"
        : "+f"(c[0]), "+f"(c[1]), "+f"(c[2]), "+f"(c[3])
        : "r"(a0), "r"(a1), "r"(a2), "r"(a3), "r"(b0), "r"(b1));
}

// ---------------------------------------------------------------------------
// Projection: C[M,128] = A[M,1024] @ W[1024,128] + bias  (M = 16384)
// Block 128x128, BK=32, 256 thr = 8 warps; warp = 16 rows x 128 cols.
// blockIdx.y selects {q,k,v}.
// ---------------------------------------------------------------------------
#define ASTR 36    // A tile [128][32] stride (36 % 32 == 4 -> conflict-free frags)
#define WSTR 132   // W tile [32][128] stride

__global__ __launch_bounds__(256)
void proj_kernel(const float* __restrict__ in_q, const float* __restrict__ in_k,
                 const float* __restrict__ in_v,
                 const float* __restrict__ Wq, const float* __restrict__ bq,
                 const float* __restrict__ Wk, const float* __restrict__ bk,
                 const float* __restrict__ Wv, const float* __restrict__ bv)
{
    __shared__ unsigned As[128 * ASTR];
    __shared__ unsigned Ws[32 * WSTR];

    const float* A; const float* W; const float* bias; float* C;
    int which = blockIdx.y;
    if (which == 0)      { A = in_q; W = Wq; bias = bq; C = g_q; }
    else if (which == 1) { A = in_k; W = Wk; bias = bk; C = g_k; }
    else                 { A = in_v; W = Wv; bias = bv; C = g_v; }

    const int row0 = blockIdx.x * 128;
    const int tid  = threadIdx.x;
    const int wid  = tid >> 5;
    const int lane = tid & 31;
    const int gid  = lane >> 2;   // 0..7
    const int tig  = lane & 3;    // 0..3
    const int m0   = wid * 16;

    float c[16][4];
    #pragma unroll
    for (int nf = 0; nf < 16; nf++)
        #pragma unroll
        for (int i = 0; i < 4; i++) c[nf][i] = 0.0f;

    for (int k0 = 0; k0 < DIN; k0 += 32) {
        // A tile 128x32
        #pragma unroll
        for (int t = 0; t < 4; t++) {
            int e = (tid + t * 256) * 4;
            int r = e >> 5;
            int cc = e & 31;
            float4 v = *(const float4*)(A + (size_t)(row0 + r) * DIN + k0 + cc);
            *(uint4*)&As[r * ASTR + cc] = f2tf4(v);
        }
        // W tile 32x128
        #pragma unroll
        for (int t = 0; t < 4; t++) {
            int e = (tid + t * 256) * 4;
            int r = e >> 7;
            int cc = e & 127;
            float4 v = *(const float4*)(W + (size_t)(k0 + r) * DH + cc);
            *(uint4*)&Ws[r * WSTR + cc] = f2tf4(v);
        }
        __syncthreads();

        #pragma unroll
        for (int ks = 0; ks < 32; ks += 8) {
            unsigned a0 = As[(m0 + gid) * ASTR + ks + tig];
            unsigned a1 = As[(m0 + gid + 8) * ASTR + ks + tig];
            unsigned a2 = As[(m0 + gid) * ASTR + ks + tig + 4];
            unsigned a3 = As[(m0 + gid + 8) * ASTR + ks + tig + 4];
            #pragma unroll
            for (int nf = 0; nf < 16; nf++) {
                unsigned b0 = Ws[(ks + tig) * WSTR + nf * 8 + gid];
                unsigned b1 = Ws[(ks + tig + 4) * WSTR + nf * 8 + gid];
                mma8(c[nf], a0, a1, a2, a3, b0, b1);
            }
        }
        __syncthreads();
    }

    // epilogue: +bias, write to C
    #pragma unroll
    for (int nf = 0; nf < 16; nf++) {
        int col = nf * 8 + 2 * tig;
        float bb0 = bias[col], bb1 = bias[col + 1];
        int r = row0 + m0 + gid;
        float2 v0 = make_float2(c[nf][0] + bb0, c[nf][1] + bb1);
        *(float2*)&C[(size_t)r * DH + col] = v0;
        float2 v1 = make_float2(c[nf][2] + bb0, c[nf][3] + bb1);
        *(float2*)&C[(size_t)(r + 8) * DH + col] = v1;
    }
}

// ---------------------------------------------------------------------------
// Flash attention, tf32 mma. Block: 256 thr = 8 warps, 128 queries (16/warp),
// K/V tiles of 64. Warp owns complete rows -> warp-local online softmax.
// All smem tiles row-major, stride 132 (frag loads conflict-free).
// ---------------------------------------------------------------------------
#define AQ 128
#define AK 64
#define QSTR 132
#define KSTR 132
#define VSTR 132
#define PSTR 68   // per-warp P patch [16][64]

__global__ __launch_bounds__(256, 1)
void attn_kernel(float* __restrict__ out)
{
    extern __shared__ unsigned smem[];
    unsigned* Qs = smem;                    // 128*132
    unsigned* Ks = Qs + 128 * QSTR;         // 64*132
    unsigned* Vs = Ks + AK * KSTR;          // 64*132
    float*    Ps = (float*)(Vs + AK * VSTR);// 8 warps * 16*68

    const int tid  = threadIdx.x;
    const int wid  = tid >> 5;
    const int lane = tid & 31;
    const int gid  = lane >> 2;
    const int tig  = lane & 3;
    const int m0   = wid * 16;

    const int batch = blockIdx.y;
    const int q0    = blockIdx.x * AQ;

    const float* qb = g_q + (size_t)batch * SEQ * DH;
    const float* kb = g_k + (size_t)batch * SEQ * DH;
    const float* vb = g_v + (size_t)batch * SEQ * DH;

    const float scale = 0.08838834764831845f;  // 1/sqrt(128), folded into Q

    // Load Q tile (pre-scaled, tf32)
    #pragma unroll
    for (int t = 0; t < 16; t++) {
        int e = (tid + t * 256) * 4;
        int r = e >> 7;
        int cc = e & 127;
        float4 v = *(const float4*)(qb + (size_t)(q0 + r) * DH + cc);
        v.x *= scale; v.y *= scale; v.z *= scale; v.w *= scale;
        *(uint4*)&Qs[r * QSTR + cc] = f2tf4(v);
    }
    __syncthreads();

    float o[16][4];
    #pragma unroll
    for (int nfo = 0; nfo < 16; nfo++)
        #pragma unroll
        for (int i = 0; i < 4; i++) o[nfo][i] = 0.0f;
    float mrow[2] = {-1e30f, -1e30f};
    float lrow[2] = {0.0f, 0.0f};

    float* Psw = Ps + wid * 16 * PSTR;

    for (int kv0 = 0; kv0 < SEQ; kv0 += AK) {
        // ---- load K, V tiles (row-major, tf32) ----
        #pragma unroll
        for (int t = 0; t < 8; t++) {
            int e = (tid + t * 256) * 4;
            int r = e >> 7;
            int cc = e & 127;
            float4 v = *(const float4*)(kb + (size_t)(kv0 + r) * DH + cc);
            *(uint4*)&Ks[r * KSTR + cc] = f2tf4(v);
        }
        #pragma unroll
        for (int t = 0; t < 8; t++) {
            int e = (tid + t * 256) * 4;
            int r = e >> 7;
            int cc = e & 127;
            float4 v = *(const float4*)(vb + (size_t)(kv0 + r) * DH + cc);
            *(uint4*)&Vs[r * VSTR + cc] = f2tf4(v);
        }
        __syncthreads();

        // ---- S = Q @ K^T  (warp tile 16 x 64) ----
        float s[8][4];
        #pragma unroll
        for (int nf = 0; nf < 8; nf++)
            #pragma unroll
            for (int i = 0; i < 4; i++) s[nf][i] = 0.0f;

        for (int ds = 0; ds < 16; ds++) {
            int d0 = ds * 8;
            unsigned a0 = Qs[(m0 + gid) * QSTR + d0 + tig];
            unsigned a1 = Qs[(m0 + gid + 8) * QSTR + d0 + tig];
            unsigned a2 = Qs[(m0 + gid) * QSTR + d0 + tig + 4];
            unsigned a3 = Qs[(m0 + gid + 8) * QSTR + d0 + tig + 4];
            #pragma unroll
            for (int nf = 0; nf < 8; nf++) {
                unsigned b0 = Ks[(nf * 8 + gid) * KSTR + d0 + tig];
                unsigned b1 = Ks[(nf * 8 + gid) * KSTR + d0 + tig + 4];
                mma8(s[nf], a0, a1, a2, a3, b0, b1);
            }
        }

        // ---- online softmax (rows gid and gid+8; reductions within quad) ----
        #pragma unroll
        for (int rr = 0; rr < 2; rr++) {
            float tm = -1e30f;
            #pragma unroll
            for (int nf = 0; nf < 8; nf++)
                tm = fmaxf(tm, fmaxf(s[nf][2 * rr], s[nf][2 * rr + 1]));
            tm = fmaxf(tm, __shfl_xor_sync(0xffffffffu, tm, 1));
            tm = fmaxf(tm, __shfl_xor_sync(0xffffffffu, tm, 2));
            float mn = fmaxf(mrow[rr], tm);
            float corr = __expf(mrow[rr] - mn);
            mrow[rr] = mn;
            float rs = 0.0f;
            #pragma unroll
            for (int nf = 0; nf < 8; nf++) {
                float p0 = __expf(s[nf][2 * rr] - mn);
                float p1 = __expf(s[nf][2 * rr + 1] - mn);
                s[nf][2 * rr] = p0;
                s[nf][2 * rr + 1] = p1;
                rs += p0 + p1;
            }
            rs += __shfl_xor_sync(0xffffffffu, rs, 1);
            rs += __shfl_xor_sync(0xffffffffu, rs, 2);
            lrow[rr] = lrow[rr] * corr + rs;
            #pragma unroll
            for (int nfo = 0; nfo < 16; nfo++) {
                o[nfo][2 * rr]     *= corr;
                o[nfo][2 * rr + 1] *= corr;
            }
        }

        // ---- P fragments -> warp-private smem (C-frag layout -> A-frag layout) ----
        #pragma unroll
        for (int nf = 0; nf < 8; nf++) {
            int cbase = nf * 8 + 2 * tig;
            Psw[gid * PSTR + cbase]           = __uint_as_float(f2tf(s[nf][0]));
            Psw[gid * PSTR + cbase + 1]       = __uint_as_float(f2tf(s[nf][1]));
            Psw[(gid + 8) * PSTR + cbase]     = __uint_as_float(f2tf(s[nf][2]));
            Psw[(gid + 8) * PSTR + cbase + 1] = __uint_as_float(f2tf(s[nf][3]));
        }
        __syncwarp();

        // ---- O += P @ V ----
        for (int ks = 0; ks < 8; ks++) {
            int k0 = ks * 8;
            unsigned pa0 = __float_as_uint(Psw[gid * PSTR + k0 + tig]);
            unsigned pa1 = __float_as_uint(Psw[(gid + 8) * PSTR + k0 + tig]);
            unsigned pa2 = __float_as_uint(Psw[gid * PSTR + k0 + tig + 4]);
            unsigned pa3 = __float_as_uint(Psw[(gid + 8) * PSTR + k0 + tig + 4]);
            #pragma unroll
            for (int nfo = 0; nfo < 16; nfo++) {
                unsigned b0 = Vs[(k0 + tig) * VSTR + nfo * 8 + gid];
                unsigned b1 = Vs[(k0 + tig + 4) * VSTR + nfo * 8 + gid];
                mma8(o[nfo], pa0, pa1, pa2, pa3, b0, b1);
            }
        }
        __syncthreads();   // everyone done with Ks/Vs before next overwrite
    }

    // ---- epilogue: normalize, store ----
    float* ob = out + (size_t)batch * SEQ * DH;
    int ra = q0 + m0 + gid;
    int rb = ra + 8;
    float ia = 1.0f / lrow[0];
    float ib = 1.0f / lrow[1];
    #pragma unroll
    for (int nfo = 0; nfo < 16; nfo++) {
        int col = nfo * 8 + 2 * tig;
        float2 va = make_float2(o[nfo][0] * ia, o[nfo][1] * ia);
        *(float2*)&ob[(size_t)ra * DH + col] = va;
        float2 vb2 = make_float2(o[nfo][2] * ib, o[nfo][3] * ib);
        *(float2*)&ob[(size_t)rb * DH + col] = vb2;
    }
}

// ---------------------------------------------------------------------------
extern "C" void kernel_launch(void* const* d_in, const int* in_sizes, int n_in,
                              void* d_out, int out_size)
{
    const float* query = (const float*)d_in[0];
    const float* key   = (const float*)d_in[1];
    const float* value = (const float*)d_in[2];
    const float* Wq    = (const float*)d_in[3];
    const float* bq    = (const float*)d_in[4];
    const float* Wk    = (const float*)d_in[5];
    const float* bk    = (const float*)d_in[6];
    const float* Wv    = (const float*)d_in[7];
    const float* bv    = (const float*)d_in[8];
    float* out = (float*)d_out;

    dim3 pgrid((BATCH * SEQ) / 128, 3);
    proj_kernel<<<pgrid, 256>>>(query, key, value, Wq, bq, Wk, bk, Wv, bv);

    size_t smem_bytes = (size_t)(128 * QSTR + AK * KSTR + AK * VSTR) * 4
                        + (size_t)8 * 16 * PSTR * 4;   // 169,984 B
    cudaFuncSetAttribute(attn_kernel,
                         cudaFuncAttributeMaxDynamicSharedMemorySize,
                         (int)smem_bytes);
    dim3 agrid(SEQ / AQ, BATCH);
    attn_kernel<<<agrid, 256, smem_bytes>>>(out);
}